// round 2
// baseline (speedup 1.0000x reference)
#include <cuda_runtime.h>
#include <cstdint>

// Problem constants (fixed by the reference)
#define IN_DIM   4096
#define OUT_DIM  1024
#define N_ROWS   16384
#define MAX_E    128          // max nnz per output row; E[nnz]=40, sigma~6.3 -> 128 is >13 sigma
#define TILE_N   8
#define STRIDE   (IN_DIM + 4) // 4100 floats: keeps 16B row alignment, subgroup lanes hit distinct banks
#define SMEM_BYTES (TILE_N * STRIDE * 4)

// Scratch (device globals are the sanctioned scratch mechanism — no allocations)
__device__ uint16_t g_ents[OUT_DIM * MAX_E]; // per-row packed entries: col (bits 0..11) | sign (bit 15)
__device__ int      g_cnt[OUT_DIM];
__device__ float    g_mag;                   // |Phi| magnitude (identical for all nonzeros)

// ---------------------------------------------------------------------------
// Kernel 1: build CSR of Phi rows. One warp per output row; ballot/popc
// compaction preserves column order -> fully deterministic entry order.
// ---------------------------------------------------------------------------
__global__ void __launch_bounds__(128) build_csr(const float* __restrict__ Phi) {
    const int wid  = blockIdx.x * (blockDim.x >> 5) + (threadIdx.x >> 5);
    const int lane = threadIdx.x & 31;
    if (wid >= OUT_DIM) return;

    const float* row = Phi + (size_t)wid * IN_DIM;
    int base = 0;
    for (int c0 = 0; c0 < IN_DIM; c0 += 32) {
        float v = row[c0 + lane];
        unsigned m = __ballot_sync(0xffffffffu, v != 0.0f);
        if (v != 0.0f) {
            int pos = base + __popc(m & ((1u << lane) - 1u));
            if (pos < MAX_E) {
                uint16_t ent = (uint16_t)((unsigned)(c0 + lane) |
                                          ((__float_as_uint(v) >> 31) << 15));
                g_ents[wid * MAX_E + pos] = ent;
            }
            g_mag = fabsf(v);   // all nonzeros share the same magnitude; benign same-value race
        }
        base += __popc(m);
    }
    if (lane == 0) g_cnt[wid] = (base < MAX_E) ? base : MAX_E;
}

// ---------------------------------------------------------------------------
// Kernel 2: out = x @ Phi.T via gather-SpMM.
// CTA stages TILE_N=8 rows of x in smem (padded stride -> conflict-free within
// each 8-lane subgroup), then 32 subgroups (8 lanes = 8 n-values each) sweep
// all 1024 output rows; ~40 gathered FMAs per output, exact fp32.
// ---------------------------------------------------------------------------
__global__ void __launch_bounds__(256, 1) jl_main(const float* __restrict__ x,
                                                  float* __restrict__ out) {
    extern __shared__ float xs[];
    const int tid = threadIdx.x;
    const int n0  = blockIdx.x * TILE_N;

    // Stage x tile: 8 rows x 4096 floats, float4 coalesced, padded smem rows.
    const float4* xg = (const float4*)x + (size_t)n0 * (IN_DIM / 4);
    #pragma unroll 4
    for (int i = tid; i < TILE_N * (IN_DIM / 4); i += 256) {
        int row = i >> 10;          // IN_DIM/4 = 1024 float4 per row
        int c4  = i & 1023;
        float4 v = xg[i];
        *(float4*)&xs[row * STRIDE + (c4 << 2)] = v;
    }
    __syncthreads();

    const unsigned magbits = __float_as_uint(g_mag);
    const int n   = tid & (TILE_N - 1);  // 0..7
    const int sub = tid >> 3;            // 0..31 subgroups
    const float* xrow = xs + n * STRIDE;

    for (int rb = 0; rb < OUT_DIM; rb += 32) {
        const int r   = rb + sub;
        const int cnt = __ldg(&g_cnt[r]);
        const uint16_t* e = g_ents + r * MAX_E;
        const uint4* e8 = (const uint4*)e;   // g_ents row base is 256B-aligned

        float a0 = 0.0f, a1 = 0.0f;
        int j = 0;
        for (; j + 8 <= cnt; j += 8) {
            uint4 p = e8[j >> 3];
            #define JL_STEP(w, sh, acc) {                                        \
                unsigned ent = ((w) >> (sh)) & 0xFFFFu;                          \
                float v = __uint_as_float(magbits ^ ((ent & 0x8000u) << 16));    \
                acc = fmaf(xrow[ent & 0xFFFu], v, acc); }
            JL_STEP(p.x, 0,  a0) JL_STEP(p.x, 16, a1)
            JL_STEP(p.y, 0,  a0) JL_STEP(p.y, 16, a1)
            JL_STEP(p.z, 0,  a0) JL_STEP(p.z, 16, a1)
            JL_STEP(p.w, 0,  a0) JL_STEP(p.w, 16, a1)
            #undef JL_STEP
        }
        for (; j < cnt; ++j) {
            unsigned ent = e[j];
            float v = __uint_as_float(magbits ^ ((ent & 0x8000u) << 16));
            a0 = fmaf(xrow[ent & 0xFFFu], v, a0);
        }
        out[(size_t)(n0 + n) * OUT_DIM + r] = a0 + a1;
    }
}

// ---------------------------------------------------------------------------
extern "C" void kernel_launch(void* const* d_in, const int* in_sizes, int n_in,
                              void* d_out, int out_size) {
    const float* x   = (const float*)d_in[0];
    const float* Phi = (const float*)d_in[1];
    // Defensive: pick pointers by size in case of input-order surprises.
    if (n_in >= 2 && in_sizes[0] == OUT_DIM * IN_DIM &&
        in_sizes[1] == N_ROWS * IN_DIM) {
        x   = (const float*)d_in[1];
        Phi = (const float*)d_in[0];
    }
    float* out = (float*)d_out;

    build_csr<<<OUT_DIM / 4, 128>>>(Phi);

    cudaFuncSetAttribute(jl_main, cudaFuncAttributeMaxDynamicSharedMemorySize,
                         SMEM_BYTES);
    jl_main<<<N_ROWS / TILE_N, 256, SMEM_BYTES>>>(x, out);
}